// round 9
// baseline (speedup 1.0000x reference)
#include <cuda_runtime.h>

#define NN 50000
#define NE 800000

// Scratch (static device arrays — no allocation allowed)
__device__ float g_hneigh[NN * 64];   // 12.8 MB
__device__ float g_h0[NN * 128];      // 25.6 MB

// ---------------------------------------------------------------------------
// Scatter-add: h_neigh[dst[e]] += efeats[e], vectorized with red.global.add.v4
// 16 threads per edge, each handling one float4 chunk of the 64-dim feature.
// ---------------------------------------------------------------------------
__global__ void scatter_kernel(const float4* __restrict__ ef,
                               const int* __restrict__ dst,
                               float* __restrict__ hn) {
    unsigned idx = blockIdx.x * blockDim.x + threadIdx.x;   // < NE*16 = 12.8M
    if (idx >= NE * 16u) return;
    unsigned e = idx >> 4;
    unsigned c = idx & 15u;
    float4 v = ef[idx];                       // efeats float4 index == e*16 + c
    float* p = hn + (size_t)__ldg(dst + e) * 64u + c * 4u;
    asm volatile("red.global.add.v4.f32 [%0], {%1,%2,%3,%4};"
                 :: "l"(p), "f"(v.x), "f"(v.y), "f"(v.z), "f"(v.w)
                 : "memory");
}

// ---------------------------------------------------------------------------
// Fused GIN layer: out = relu(relu([A0|A1] @ W1 + b1) @ W2 + b2)
//   A0: [NN, D_IN-64]   (nfeats for layer 0, h0 for layer 1)
//   A1: [NN, 64]        (h_neigh)
// One block = 64 nodes x 128 outputs. 256 threads, 4x8 register tile each.
// Both weight matrices staged in shared; intermediate T kept in shared.
// ---------------------------------------------------------------------------
template <int D_IN>
__global__ __launch_bounds__(256)
void layer_kernel(const float* __restrict__ A0,
                  const float* __restrict__ A1,
                  const float* __restrict__ W1, const float* __restrict__ b1,
                  const float* __restrict__ W2, const float* __restrict__ b2,
                  float* __restrict__ out) {
    constexpr int D0 = D_IN - 64;
    constexpr int XS = D_IN + 4;     // padded row stride (16B aligned, no bank conflicts)
    constexpr int TS = 132;          // T row stride (128 + 4)

    extern __shared__ float smem[];
    float* sW = smem;                     // D_IN*128 floats (reused for W2: 128*128)
    float* sX = sW + D_IN * 128;          // 64 * XS
    float* sT = sX + 64 * XS;             // 64 * TS

    const int tid = threadIdx.x;
    const int tx = tid & 15;              // column group: cols tx*8 .. tx*8+7
    const int ty = tid >> 4;              // row group:    rows ty*4 .. ty*4+3
    const int nodebase = blockIdx.x * 64;

    // ---- stage W1 ----
    {
        const float4* w4 = (const float4*)W1;
        float4* s4 = (float4*)sW;
        for (int i = tid; i < D_IN * 128 / 4; i += 256) s4[i] = w4[i];
    }
    // ---- stage X = [A0 | A1] (zero-padded past NN) ----
    for (int i = tid; i < 64 * D_IN; i += 256) {
        int r = i / D_IN;
        int c = i - r * D_IN;
        int node = nodebase + r;
        float v = 0.f;
        if (node < NN)
            v = (c < D0) ? A0[(size_t)node * D0 + c]
                         : A1[(size_t)node * 64 + (c - D0)];
        sX[r * XS + c] = v;
    }
    __syncthreads();

    float acc[4][8];

    // ================= GEMM1: T = relu(X @ W1 + b1) =================
    #pragma unroll
    for (int i = 0; i < 4; i++)
        #pragma unroll
        for (int j = 0; j < 8; j++) acc[i][j] = 0.f;
    {
        const float* xA = sX + (ty * 4) * XS;
        #pragma unroll 2
        for (int k = 0; k < D_IN; k += 4) {
            float4 a0 = *(const float4*)(xA + k);
            float4 a1 = *(const float4*)(xA + XS + k);
            float4 a2 = *(const float4*)(xA + 2 * XS + k);
            float4 a3 = *(const float4*)(xA + 3 * XS + k);
            const float* wk = sW + k * 128 + tx * 8;
            #pragma unroll
            for (int kk = 0; kk < 4; kk++) {
                float4 bL = *(const float4*)(wk + kk * 128);
                float4 bH = *(const float4*)(wk + kk * 128 + 4);
                float bb[8] = {bL.x, bL.y, bL.z, bL.w, bH.x, bH.y, bH.z, bH.w};
                float av0 = ((const float*)&a0)[kk];
                float av1 = ((const float*)&a1)[kk];
                float av2 = ((const float*)&a2)[kk];
                float av3 = ((const float*)&a3)[kk];
                #pragma unroll
                for (int j = 0; j < 8; j++) {
                    acc[0][j] = fmaf(av0, bb[j], acc[0][j]);
                    acc[1][j] = fmaf(av1, bb[j], acc[1][j]);
                    acc[2][j] = fmaf(av2, bb[j], acc[2][j]);
                    acc[3][j] = fmaf(av3, bb[j], acc[3][j]);
                }
            }
        }
    }
    __syncthreads();   // all threads done reading sW/sX before sW is reused

    // epilogue 1 -> sT (relu)
    #pragma unroll
    for (int j = 0; j < 8; j++) {
        float bias = __ldg(b1 + tx * 8 + j);
        #pragma unroll
        for (int i = 0; i < 4; i++) {
            float v = acc[i][j] + bias;
            sT[(ty * 4 + i) * TS + tx * 8 + j] = fmaxf(v, 0.f);
        }
    }
    // ---- stage W2 (overwrites W1 region) ----
    {
        const float4* w4 = (const float4*)W2;
        float4* s4 = (float4*)sW;
        for (int i = tid; i < 128 * 128 / 4; i += 256) s4[i] = w4[i];
    }
    __syncthreads();

    // ================= GEMM2: out = relu(T @ W2 + b2) =================
    #pragma unroll
    for (int i = 0; i < 4; i++)
        #pragma unroll
        for (int j = 0; j < 8; j++) acc[i][j] = 0.f;
    {
        const float* tA = sT + (ty * 4) * TS;
        #pragma unroll 2
        for (int k = 0; k < 128; k += 4) {
            float4 a0 = *(const float4*)(tA + k);
            float4 a1 = *(const float4*)(tA + TS + k);
            float4 a2 = *(const float4*)(tA + 2 * TS + k);
            float4 a3 = *(const float4*)(tA + 3 * TS + k);
            const float* wk = sW + k * 128 + tx * 8;
            #pragma unroll
            for (int kk = 0; kk < 4; kk++) {
                float4 bL = *(const float4*)(wk + kk * 128);
                float4 bH = *(const float4*)(wk + kk * 128 + 4);
                float bb[8] = {bL.x, bL.y, bL.z, bL.w, bH.x, bH.y, bH.z, bH.w};
                float av0 = ((const float*)&a0)[kk];
                float av1 = ((const float*)&a1)[kk];
                float av2 = ((const float*)&a2)[kk];
                float av3 = ((const float*)&a3)[kk];
                #pragma unroll
                for (int j = 0; j < 8; j++) {
                    acc[0][j] = fmaf(av0, bb[j], acc[0][j]);
                    acc[1][j] = fmaf(av1, bb[j], acc[1][j]);
                    acc[2][j] = fmaf(av2, bb[j], acc[2][j]);
                    acc[3][j] = fmaf(av3, bb[j], acc[3][j]);
                }
            }
        }
    }
    // epilogue 2 -> global (relu), float4 stores
    float bias2[8];
    #pragma unroll
    for (int j = 0; j < 8; j++) bias2[j] = __ldg(b2 + tx * 8 + j);
    #pragma unroll
    for (int i = 0; i < 4; i++) {
        int node = nodebase + ty * 4 + i;
        if (node < NN) {
            float4 o0, o1;
            o0.x = fmaxf(acc[i][0] + bias2[0], 0.f);
            o0.y = fmaxf(acc[i][1] + bias2[1], 0.f);
            o0.z = fmaxf(acc[i][2] + bias2[2], 0.f);
            o0.w = fmaxf(acc[i][3] + bias2[3], 0.f);
            o1.x = fmaxf(acc[i][4] + bias2[4], 0.f);
            o1.y = fmaxf(acc[i][5] + bias2[5], 0.f);
            o1.z = fmaxf(acc[i][6] + bias2[6], 0.f);
            o1.w = fmaxf(acc[i][7] + bias2[7], 0.f);
            float* po = out + (size_t)node * 128 + tx * 8;
            *(float4*)(po) = o0;
            *(float4*)(po + 4) = o1;
        }
    }
}

// shared-memory sizes in bytes
static constexpr int SMEM0 = (128 * 128 + 64 * (128 + 4) + 64 * 132) * 4;  // 133 KB
static constexpr int SMEM1 = (192 * 128 + 64 * (192 + 4) + 64 * 132) * 4;  // 182 KB

extern "C" void kernel_launch(void* const* d_in, const int* in_sizes, int n_in,
                              void* d_out, int out_size) {
    const float* nfeats = (const float*)d_in[0];
    const float* efeats = (const float*)d_in[1];
    const int*   dst    = (const int*)d_in[2];
    const float* W1_0   = (const float*)d_in[3];
    const float* b1_0   = (const float*)d_in[4];
    const float* W2_0   = (const float*)d_in[5];
    const float* b2_0   = (const float*)d_in[6];
    const float* W1_1   = (const float*)d_in[7];
    const float* b1_1   = (const float*)d_in[8];
    const float* W2_1   = (const float*)d_in[9];
    const float* b2_1   = (const float*)d_in[10];

    void* hn_ptr = nullptr;
    void* h0_ptr = nullptr;
    cudaGetSymbolAddress(&hn_ptr, g_hneigh);
    cudaGetSymbolAddress(&h0_ptr, g_h0);

    cudaFuncSetAttribute(layer_kernel<128>,
                         cudaFuncAttributeMaxDynamicSharedMemorySize, SMEM0);
    cudaFuncSetAttribute(layer_kernel<192>,
                         cudaFuncAttributeMaxDynamicSharedMemorySize, SMEM1);

    // zero the h_neigh accumulator
    cudaMemsetAsync(hn_ptr, 0, sizeof(float) * NN * 64);

    // scatter-add edge features onto destination nodes
    unsigned total = NE * 16u;
    scatter_kernel<<<(total + 255) / 256, 256>>>(
        (const float4*)efeats, dst, (float*)hn_ptr);

    // layer 0: [nfeats | h_neigh] -> h0
    layer_kernel<128><<<(NN + 63) / 64, 256, SMEM0>>>(
        nfeats, (const float*)hn_ptr, W1_0, b1_0, W2_0, b2_0, (float*)h0_ptr);

    // layer 1: [h0 | h_neigh] -> out
    layer_kernel<192><<<(NN + 63) / 64, 256, SMEM1>>>(
        (const float*)h0_ptr, (const float*)hn_ptr, W1_1, b1_1, W2_1, b2_1,
        (float*)d_out);
}

// round 10
// speedup vs baseline: 1.9972x; 1.9972x over previous
#include <cuda_runtime.h>

#define NN 50000
#define NE 800000

// Scratch (static device arrays — no allocation allowed)
__device__ float g_hneigh[NN * 64];   // 12.8 MB
__device__ float g_h0[NN * 128];      // 25.6 MB

// ---------------------------------------------------------------------------
// f32x2 packed-FMA helpers (Blackwell FFMA2 — only reachable via PTX)
// ---------------------------------------------------------------------------
__device__ __forceinline__ unsigned long long fma2(unsigned long long a,
                                                   unsigned long long b,
                                                   unsigned long long c) {
    unsigned long long d;
    asm("fma.rn.f32x2 %0, %1, %2, %3;" : "=l"(d) : "l"(a), "l"(b), "l"(c));
    return d;
}
__device__ __forceinline__ unsigned long long pk2(float x) {
    unsigned long long r;
    asm("mov.b64 %0, {%1, %1};" : "=l"(r) : "f"(x));
    return r;
}
__device__ __forceinline__ float2 upk(unsigned long long v) {
    float2 f;
    asm("mov.b64 {%0, %1}, %2;" : "=f"(f.x), "=f"(f.y) : "l"(v));
    return f;
}

// ---------------------------------------------------------------------------
// Scatter-add: h_neigh[dst[e]] += efeats[e], via red.global.add.v4.f32
// ---------------------------------------------------------------------------
__global__ void scatter_kernel(const float4* __restrict__ ef,
                               const int* __restrict__ dst,
                               float* __restrict__ hn) {
    unsigned idx = blockIdx.x * blockDim.x + threadIdx.x;   // < NE*16 = 12.8M
    if (idx >= NE * 16u) return;
    unsigned e = idx >> 4;
    unsigned c = idx & 15u;
    float4 v = ef[idx];
    float* p = hn + (size_t)__ldg(dst + e) * 64u + c * 4u;
    asm volatile("red.global.add.v4.f32 [%0], {%1,%2,%3,%4};"
                 :: "l"(p), "f"(v.x), "f"(v.y), "f"(v.z), "f"(v.w)
                 : "memory");
}

// ---------------------------------------------------------------------------
// Shared-memory GEMM tile: acc[8][4 pairs] += A[128,D] @ W[D,128]
// 256 threads: tx (0..15) -> cols tx*8..+7 (4 f32x2 pairs), ty (0..15) -> rows ty*8..+7
// W pairs load directly as ulonglong2 from shared; A scalar duplicated via mov.b64.
// ---------------------------------------------------------------------------
template <int D, int STRIDE>
__device__ __forceinline__ void gemm_tile(const float* __restrict__ sA,
                                          const float* __restrict__ sW,
                                          int tx, int ty,
                                          unsigned long long acc[8][4]) {
    #pragma unroll
    for (int r = 0; r < 8; r++)
        #pragma unroll
        for (int p = 0; p < 4; p++) acc[r][p] = 0ull;

    const float* xA = sA + (ty * 8) * STRIDE;
    #pragma unroll 2
    for (int k = 0; k < D; k += 4) {
        float4 a[8];
        #pragma unroll
        for (int r = 0; r < 8; r++)
            a[r] = *(const float4*)(xA + r * STRIDE + k);
        const float* wk = sW + k * 128 + tx * 8;
        #pragma unroll
        for (int kk = 0; kk < 4; kk++) {
            ulonglong2 w0 = *(const ulonglong2*)(wk + kk * 128);
            ulonglong2 w1 = *(const ulonglong2*)(wk + kk * 128 + 4);
            #pragma unroll
            for (int r = 0; r < 8; r++) {
                float av = ((const float*)&a[r])[kk];
                unsigned long long ap = pk2(av);
                acc[r][0] = fma2(ap, w0.x, acc[r][0]);
                acc[r][1] = fma2(ap, w0.y, acc[r][1]);
                acc[r][2] = fma2(ap, w1.x, acc[r][2]);
                acc[r][3] = fma2(ap, w1.y, acc[r][3]);
            }
        }
    }
}

// ---------------------------------------------------------------------------
// Fused GIN layer: out = relu(relu([A0|A1] @ W1 + b1) @ W2 + b2)
// One block = 128 nodes x 128 outputs, 256 threads, 8x8 register tile.
// T (intermediate) reuses the X smem region after GEMM1.
// ---------------------------------------------------------------------------
template <int D_IN>
__global__ __launch_bounds__(256)
void layer_kernel(const float* __restrict__ A0,
                  const float* __restrict__ A1,
                  const float* __restrict__ W1, const float* __restrict__ b1,
                  const float* __restrict__ W2, const float* __restrict__ b2,
                  float* __restrict__ out) {
    constexpr int D0 = D_IN - 64;
    constexpr int XS = D_IN + 4;     // padded row stride (bytes multiple of 16)
    constexpr int TS = 132;          // T row stride

    extern __shared__ float smem[];
    float* sW = smem;                     // D_IN*128 floats (reused for W2: 128*128)
    float* sX = sW + D_IN * 128;          // 128 * XS  (reused for T: 128 * TS)
    float* sT = sX;

    const int tid = threadIdx.x;
    const int tx = tid & 15;
    const int ty = tid >> 4;
    const int nodebase = blockIdx.x * 128;

    // ---- stage W1 ----
    {
        const float4* w4 = (const float4*)W1;
        float4* s4 = (float4*)sW;
        #pragma unroll 4
        for (int i = tid; i < D_IN * 128 / 4; i += 256) s4[i] = w4[i];
    }
    // ---- stage X = [A0 | A1], float4 granularity, zero past NN ----
    {
        constexpr int C4 = D_IN / 4;
        for (int i = tid; i < 128 * C4; i += 256) {
            int r = i / C4;
            int c = (i - r * C4) * 4;
            int node = nodebase + r;
            float4 v = make_float4(0.f, 0.f, 0.f, 0.f);
            if (node < NN)
                v = (c < D0) ? *(const float4*)(A0 + (size_t)node * D0 + c)
                             : *(const float4*)(A1 + (size_t)node * 64 + (c - D0));
            *(float4*)(sX + r * XS + c) = v;
        }
    }
    __syncthreads();

    unsigned long long acc[8][4];

    // ================= GEMM1: T = relu(X @ W1 + b1) =================
    gemm_tile<D_IN, XS>(sX, sW, tx, ty, acc);
    __syncthreads();   // done reading sX / sW before both regions are reused

    // epilogue 1 -> sT (relu); stage W2 into sW
    {
        float2 bias[4];
        #pragma unroll
        for (int p = 0; p < 4; p++)
            bias[p] = make_float2(__ldg(b1 + tx * 8 + 2 * p),
                                  __ldg(b1 + tx * 8 + 2 * p + 1));
        #pragma unroll
        for (int r = 0; r < 8; r++) {
            float* row = sT + (ty * 8 + r) * TS + tx * 8;
            #pragma unroll
            for (int p = 0; p < 4; p++) {
                float2 v = upk(acc[r][p]);
                v.x = fmaxf(v.x + bias[p].x, 0.f);
                v.y = fmaxf(v.y + bias[p].y, 0.f);
                *(float2*)(row + 2 * p) = v;
            }
        }
    }
    {
        const float4* w4 = (const float4*)W2;
        float4* s4 = (float4*)sW;
        #pragma unroll 4
        for (int i = tid; i < 128 * 128 / 4; i += 256) s4[i] = w4[i];
    }
    __syncthreads();

    // ================= GEMM2: out = relu(T @ W2 + b2) =================
    gemm_tile<128, TS>(sT, sW, tx, ty, acc);

    // epilogue 2 -> global (relu), float4 stores
    {
        float2 bias[4];
        #pragma unroll
        for (int p = 0; p < 4; p++)
            bias[p] = make_float2(__ldg(b2 + tx * 8 + 2 * p),
                                  __ldg(b2 + tx * 8 + 2 * p + 1));
        #pragma unroll
        for (int r = 0; r < 8; r++) {
            int node = nodebase + ty * 8 + r;
            if (node < NN) {
                float2 v0 = upk(acc[r][0]), v1 = upk(acc[r][1]);
                float2 v2 = upk(acc[r][2]), v3 = upk(acc[r][3]);
                float4 o0, o1;
                o0.x = fmaxf(v0.x + bias[0].x, 0.f);
                o0.y = fmaxf(v0.y + bias[0].y, 0.f);
                o0.z = fmaxf(v1.x + bias[1].x, 0.f);
                o0.w = fmaxf(v1.y + bias[1].y, 0.f);
                o1.x = fmaxf(v2.x + bias[2].x, 0.f);
                o1.y = fmaxf(v2.y + bias[2].y, 0.f);
                o1.z = fmaxf(v3.x + bias[3].x, 0.f);
                o1.w = fmaxf(v3.y + bias[3].y, 0.f);
                float* po = out + (size_t)node * 128 + tx * 8;
                *(float4*)(po) = o0;
                *(float4*)(po + 4) = o1;
            }
        }
    }
}

// shared-memory sizes in bytes
static constexpr int SMEM0 = (128 * 128 + 128 * 132) * 4;  // 133120 B
static constexpr int SMEM1 = (192 * 128 + 128 * 196) * 4;  // 198656 B

extern "C" void kernel_launch(void* const* d_in, const int* in_sizes, int n_in,
                              void* d_out, int out_size) {
    const float* nfeats = (const float*)d_in[0];
    const float* efeats = (const float*)d_in[1];
    const int*   dst    = (const int*)d_in[2];
    const float* W1_0   = (const float*)d_in[3];
    const float* b1_0   = (const float*)d_in[4];
    const float* W2_0   = (const float*)d_in[5];
    const float* b2_0   = (const float*)d_in[6];
    const float* W1_1   = (const float*)d_in[7];
    const float* b1_1   = (const float*)d_in[8];
    const float* W2_1   = (const float*)d_in[9];
    const float* b2_1   = (const float*)d_in[10];

    void* hn_ptr = nullptr;
    void* h0_ptr = nullptr;
    cudaGetSymbolAddress(&hn_ptr, g_hneigh);
    cudaGetSymbolAddress(&h0_ptr, g_h0);

    cudaFuncSetAttribute(layer_kernel<128>,
                         cudaFuncAttributeMaxDynamicSharedMemorySize, SMEM0);
    cudaFuncSetAttribute(layer_kernel<192>,
                         cudaFuncAttributeMaxDynamicSharedMemorySize, SMEM1);

    // zero the h_neigh accumulator
    cudaMemsetAsync(hn_ptr, 0, sizeof(float) * NN * 64);

    // scatter-add edge features onto destination nodes
    unsigned total = NE * 16u;
    scatter_kernel<<<(total + 255) / 256, 256>>>(
        (const float4*)efeats, dst, (float*)hn_ptr);

    // layer 0: [nfeats | h_neigh] -> h0
    layer_kernel<128><<<(NN + 127) / 128, 256, SMEM0>>>(
        nfeats, (const float*)hn_ptr, W1_0, b1_0, W2_0, b2_0, (float*)h0_ptr);

    // layer 1: [h0 | h_neigh] -> out
    layer_kernel<192><<<(NN + 127) / 128, 256, SMEM1>>>(
        (const float*)h0_ptr, (const float*)hn_ptr, W1_1, b1_1, W2_1, b2_1,
        (float*)d_out);
}